// round 1
// baseline (speedup 1.0000x reference)
#include <cuda_runtime.h>

#define BB   512          // batch
#define TM1  63           // T-1
#define NI   512          // input size N
#define HH   256          // hidden H
#define H4   1024         // 4*H
#define KTOT 768          // N + H (GEMM K)

#define OFF_IE 16515072UL                 // B*TM1*NI
#define OFF_W  24772608UL                 // OFF_IE + B*TM1*HH

// scratch (device globals: no allocations allowed)
__device__ float g_t2[BB * TM1 * NI];     // [b][s][n], 66 MB
__device__ float g_h[BB * HH];
__device__ float g_c[BB * HH];
__device__ float g_gates[BB * H4];

__device__ __forceinline__ float ftanh(float x) {
    // tanh(x) = 1 - 2/(exp(2x)+1); robust at +-inf, rel err ~2^-22
    float e = __expf(2.0f * x);
    return 1.0f - __fdividef(2.0f, e + 1.0f);
}
__device__ __forceinline__ float fsig(float x) {
    return __fdividef(1.0f, 1.0f + __expf(-x));
}

__global__ void zero_hc_kernel() {
    int i = blockIdx.x * blockDim.x + threadIdx.x;
    if (i < BB * HH) { g_h[i] = 0.0f; g_c[i] = 0.0f; }
}

// t2[b][s][n] = sum_t x[b][t][n] * Wd[s][t] + bd[s]
// grid (B, NI/128), block 128. One thread per (b,n), acc[64] in regs.
__global__ void t2_kernel(const float* __restrict__ x,
                          const float* __restrict__ Wd,
                          const float* __restrict__ bd) {
    __shared__ __align__(16) float wdT[TM1 * 64];  // [t][s], s padded to 64
    int tid = threadIdx.x;
    for (int idx = tid; idx < TM1 * 64; idx += 128) {
        int t = idx >> 6, s = idx & 63;
        wdT[idx] = (s < TM1) ? Wd[s * TM1 + t] : 0.0f;
    }
    __syncthreads();

    int b = blockIdx.x;
    int n = blockIdx.y * 128 + tid;
    float acc[64];
#pragma unroll
    for (int s = 0; s < 64; s++) acc[s] = 0.0f;

    const float* xp = x + (size_t)(b * TM1) * NI + n;
    for (int t = 0; t < TM1; t++) {
        float xv = xp[(size_t)t * NI];
        const float4* wrow = reinterpret_cast<const float4*>(&wdT[t * 64]);
#pragma unroll
        for (int q = 0; q < 16; q++) {
            float4 w = wrow[q];
            acc[q * 4 + 0] += xv * w.x;
            acc[q * 4 + 1] += xv * w.y;
            acc[q * 4 + 2] += xv * w.z;
            acc[q * 4 + 3] += xv * w.w;
        }
    }
    float* t2p = g_t2 + (size_t)(b * TM1) * NI + n;
#pragma unroll
    for (int s = 0; s < TM1; s++) t2p[(size_t)s * NI] = acc[s] + bd[s];
}

// Fused per-step attention: t1 = [h|c]@Wc^T+bc, scores, softmax over n,
// wx = attn*x_t; writes input_weighted and weight slices.
// grid B, block 512 (one thread per n).
__global__ void attn_kernel(const float* __restrict__ x,
                            const float* __restrict__ Wc,
                            const float* __restrict__ bc,
                            const float* __restrict__ Wa,
                            const float* __restrict__ ba,
                            float* __restrict__ out, int t) {
    __shared__ float hs[2 * HH];
    __shared__ float t1s[64];
    __shared__ float was[64];
    __shared__ float red[512];

    int tid = threadIdx.x;
    int b = blockIdx.x;

    hs[tid] = (tid < HH) ? g_h[b * HH + tid] : g_c[b * HH + tid - HH];
    if (tid < TM1) was[tid] = Wa[tid];
    __syncthreads();

    // t1: 16 warps x 4 s-values each (s<63)
    int w = tid >> 5, lane = tid & 31;
#pragma unroll
    for (int u = 0; u < 4; u++) {
        int s = w * 4 + u;
        if (s < TM1) {
            float acc = 0.0f;
            const float* wc = Wc + s * (2 * HH);
#pragma unroll
            for (int k = 0; k < 16; k++) {
                int j = lane + k * 32;
                acc += hs[j] * wc[j];
            }
#pragma unroll
            for (int off = 16; off; off >>= 1)
                acc += __shfl_xor_sync(0xffffffffu, acc, off);
            if (lane == 0) t1s[s] = acc + bc[s];
        }
    }
    __syncthreads();

    // scores[n] = sum_s wa[s]*tanh(t1[s] + t2[b][s][n]) + ba
    float sc = ba[0];
    const float* t2p = g_t2 + (size_t)(b * TM1) * NI + tid;
#pragma unroll 7
    for (int s = 0; s < TM1; s++) {
        sc += was[s] * ftanh(t1s[s] + t2p[(size_t)s * NI]);
    }

    // block softmax over n=512
    red[tid] = sc;
    __syncthreads();
#pragma unroll
    for (int off = 256; off > 0; off >>= 1) {
        if (tid < off) red[tid] = fmaxf(red[tid], red[tid + off]);
        __syncthreads();
    }
    float m = red[0];
    __syncthreads();
    float e = __expf(sc - m);
    red[tid] = e;
    __syncthreads();
#pragma unroll
    for (int off = 256; off > 0; off >>= 1) {
        if (tid < off) red[tid] += red[tid + off];
        __syncthreads();
    }
    float attn = e / red[0];

    float xv = x[(size_t)(b * TM1 + t) * NI + tid];
    float wx = attn * xv;
    out[(size_t)(b * TM1 + t) * NI + tid] = wx;            // input_weighted
    out[OFF_W + (size_t)(b * TM1 + t) * NI + tid] = attn;  // weight
}

// gates[b][g] = [wx|h] @ [W_ih|W_hh]^T + b_ih + b_hh
// M=512, N=1024, K=768; 64x64 tile, BK=16, 4x4 per thread.
#define BM 64
#define BN 64
#define BK 16
__global__ void gemm_kernel(const float* __restrict__ wx_all,  // d_out base
                            const float* __restrict__ Wih,
                            const float* __restrict__ Whh,
                            const float* __restrict__ bih,
                            const float* __restrict__ bhh, int t) {
    __shared__ __align__(16) float As[BK][72];  // [k][m]
    __shared__ __align__(16) float Bs[BK][72];  // [k][n]

    int tid = threadIdx.x;
    int tx = tid & 15, ty = tid >> 4;
    int b0 = blockIdx.y * BM;
    int g0 = blockIdx.x * BN;
    float acc[4][4] = {};

    int lm = tid >> 2;         // 0..63 row within tile
    int lk = (tid & 3) * 4;    // 0,4,8,12 k offset

    for (int kt = 0; kt < KTOT; kt += BK) {
        // A tile: [wx | h], row = b0+lm
        const float* ap;
        int brow = b0 + lm;
        if (kt < NI) ap = wx_all + (size_t)(brow * TM1 + t) * NI + kt + lk;
        else         ap = g_h + brow * HH + (kt - NI) + lk;
        float4 av = *reinterpret_cast<const float4*>(ap);
        As[lk + 0][lm] = av.x; As[lk + 1][lm] = av.y;
        As[lk + 2][lm] = av.z; As[lk + 3][lm] = av.w;

        // B tile: [W_ih | W_hh], row = g0+lm
        const float* bp;
        int grow = g0 + lm;
        if (kt < NI) bp = Wih + grow * NI + kt + lk;
        else         bp = Whh + grow * HH + (kt - NI) + lk;
        float4 bv = *reinterpret_cast<const float4*>(bp);
        Bs[lk + 0][lm] = bv.x; Bs[lk + 1][lm] = bv.y;
        Bs[lk + 2][lm] = bv.z; Bs[lk + 3][lm] = bv.w;
        __syncthreads();

#pragma unroll
        for (int k = 0; k < BK; k++) {
            float4 a  = *reinterpret_cast<const float4*>(&As[k][ty * 4]);
            float4 bb = *reinterpret_cast<const float4*>(&Bs[k][tx * 4]);
            float am[4] = {a.x, a.y, a.z, a.w};
            float bn[4] = {bb.x, bb.y, bb.z, bb.w};
#pragma unroll
            for (int i = 0; i < 4; i++)
#pragma unroll
                for (int j = 0; j < 4; j++)
                    acc[i][j] += am[i] * bn[j];
        }
        __syncthreads();
    }

#pragma unroll
    for (int i = 0; i < 4; i++) {
        int br = b0 + ty * 4 + i;
#pragma unroll
        for (int j = 0; j < 4; j++) {
            int g = g0 + tx * 4 + j;
            g_gates[(size_t)br * H4 + g] = acc[i][j] + bih[g] + bhh[g];
        }
    }
}

// LSTM cell update + input_encoded write. One thread per (b, h).
__global__ void lstm_kernel(float* __restrict__ out, int t) {
    int idx = blockIdx.x * 256 + threadIdx.x;   // == b*HH + hh
    int b = idx >> 8;
    int hh = idx & 255;
    const float* gp = g_gates + (size_t)b * H4;
    float ig = fsig(gp[hh]);
    float fg = fsig(gp[HH + hh]);
    float gg = ftanh(gp[2 * HH + hh]);
    float og = fsig(gp[3 * HH + hh]);
    float c = fg * g_c[idx] + ig * gg;
    float h = og * ftanh(c);
    g_c[idx] = c;
    g_h[idx] = h;
    out[OFF_IE + (size_t)(b * TM1 + t) * HH + hh] = h;
}

extern "C" void kernel_launch(void* const* d_in, const int* in_sizes, int n_in,
                              void* d_out, int out_size) {
    const float* x   = (const float*)d_in[0];
    const float* Wih = (const float*)d_in[1];
    const float* Whh = (const float*)d_in[2];
    const float* bih = (const float*)d_in[3];
    const float* bhh = (const float*)d_in[4];
    const float* Wc  = (const float*)d_in[5];
    const float* bc  = (const float*)d_in[6];
    const float* Wd  = (const float*)d_in[7];
    const float* bd  = (const float*)d_in[8];
    const float* Wa  = (const float*)d_in[9];
    const float* ba  = (const float*)d_in[10];
    float* out = (float*)d_out;

    zero_hc_kernel<<<(BB * HH + 255) / 256, 256>>>();
    t2_kernel<<<dim3(BB, NI / 128), 128>>>(x, Wd, bd);

    for (int t = 0; t < TM1; t++) {
        attn_kernel<<<BB, 512>>>(x, Wc, bc, Wa, ba, out, t);
        gemm_kernel<<<dim3(16, 8), 256>>>(out, Wih, Whh, bih, bhh, t);
        lstm_kernel<<<BB, 256>>>(out, t);
    }
}